// round 2
// baseline (speedup 1.0000x reference)
#include <cuda_runtime.h>
#include <cuda_bf16.h>

// LengthRegulator: B=16, T=512, D=384, target_len=4096, fp32.
// out[b, t, :] = x[b, idx(b,t), :] where idx = searchsorted_right(cumsum(max(dur,1)), t),
// clamped to T-1; zero where t >= total(b).
//
// Single fused kernel: each block = 1 batch x 64 output rows.
//  - recompute the batch's 512-wide inclusive scan in shared (cheap vs. store traffic)
//  - 64 binary searches (threads 0..63) -> s_idx[]
//  - stream 64 rows x 96 float4 stores, gather-reads of x served from L2 (x = 12.6MB << 126MB L2)

namespace {

constexpr int B  = 16;
constexpr int T  = 512;
constexpr int D  = 384;
constexpr int TL = 4096;
constexpr int D4 = D / 4;        // 96 float4 per row
constexpr int ROWS = 64;         // output rows per block
constexpr int THREADS = 512;

__global__ __launch_bounds__(THREADS, 2)
void length_regulator_kernel(const float* __restrict__ x,
                             const int* __restrict__ durations,
                             float* __restrict__ out)
{
    __shared__ int s_cum[T];
    __shared__ int s_warp[16];
    __shared__ int s_idx[ROWS];   // source row per output row, -1 => write zeros

    const int b   = blockIdx.y;
    const int tid = threadIdx.x;
    const int lane = tid & 31;
    const int w    = tid >> 5;

    // ---- inclusive scan of max(dur,1) over T=512 (one element per thread) ----
    int d = durations[b * T + tid];
    d = (d < 1) ? 1 : d;

    int v = d;
    #pragma unroll
    for (int o = 1; o < 32; o <<= 1) {
        int n = __shfl_up_sync(0xffffffffu, v, o);
        if (lane >= o) v += n;
    }
    if (lane == 31) s_warp[w] = v;
    __syncthreads();
    if (w == 0 && lane < 16) {
        int wv = s_warp[lane];
        #pragma unroll
        for (int o = 1; o < 16; o <<= 1) {
            int n = __shfl_up_sync(0x0000ffffu, wv, o);
            if (lane >= o) wv += n;
        }
        s_warp[lane] = wv;
    }
    __syncthreads();
    const int add = (w > 0) ? s_warp[w - 1] : 0;
    s_cum[tid] = v + add;
    __syncthreads();

    const int total = s_cum[T - 1];
    const int t0 = blockIdx.x * ROWS;

    // ---- binary search (searchsorted right) for each of this block's 64 rows ----
    if (tid < ROWS) {
        const int t = t0 + tid;
        int lo = 0, hi = T;                  // find first j with cum[j] > t
        while (lo < hi) {
            int mid = (lo + hi) >> 1;
            if (s_cum[mid] <= t) lo = mid + 1; else hi = mid;
        }
        int idx = (lo < T - 1) ? lo : (T - 1);
        s_idx[tid] = (t < total) ? idx : -1;
    }
    __syncthreads();

    // ---- stream: 64 rows x 96 float4 = 6144 float4, 12 per thread ----
    const float4* __restrict__ xb = reinterpret_cast<const float4*>(x) + (size_t)b * T * D4;
    float4* __restrict__ ob = reinterpret_cast<float4*>(out) + ((size_t)b * TL + t0) * D4;

    #pragma unroll
    for (int k = 0; k < (ROWS * D4) / THREADS; ++k) {
        const int i = k * THREADS + tid;
        const int r = i / D4;
        const int c = i - r * D4;
        const int idx = s_idx[r];
        float4 val;
        if (idx >= 0) {
            val = xb[idx * D4 + c];
        } else {
            val = make_float4(0.f, 0.f, 0.f, 0.f);
        }
        ob[(size_t)r * D4 + c] = val;
    }
}

} // namespace

extern "C" void kernel_launch(void* const* d_in, const int* in_sizes, int n_in,
                              void* d_out, int out_size)
{
    const float* x          = (const float*)d_in[0];
    const int*   durations  = (const int*)d_in[1];
    float*       out        = (float*)d_out;

    dim3 grid(TL / ROWS, B);   // (64, 16)
    length_regulator_kernel<<<grid, THREADS>>>(x, durations, out);
}